// round 8
// baseline (speedup 1.0000x reference)
#include <cuda_runtime.h>
#include <cuda_bf16.h>
#include <cstdint>

// Per-row mode of x[N, 64], values guaranteed integer in {0..7}.
//
// R7: best-of-measured recombination. 256-thread blocks (R3's shape gave the
// best observed DRAM util: finer CTA grain for wave balancing), 16 rows/warp,
// MLP=8, default-cached __ldg loads, verified c==0 epilogue.
//  - per-element update: FFMA magic (x*4 + 2^23 -> 4v in low mantissa bits),
//    h += 1 << (bits & 0x1C) on a 32-bit nibble histogram (max count 8).
//  - widen nibbles->bytes, 3-level shfl_xor reduce over the 8 lanes of a row.
//  - distributed mode: lane j owns value j, key=(cnt<<3)|(7-j), max-reduce
//    -> highest count, smallest value on ties.

__device__ __forceinline__ unsigned acc_nib(unsigned h, float x) {
    unsigned b = __float_as_uint(fmaf(x, 4.0f, 8388608.0f));
    return h + (1u << (b & 0x1Cu));
}

__device__ __forceinline__ unsigned hist8(const float4& a, const float4& b) {
    unsigned hA = 0, hB = 0;
    hA = acc_nib(hA, a.x); hB = acc_nib(hB, b.x);
    hA = acc_nib(hA, a.y); hB = acc_nib(hB, b.y);
    hA = acc_nib(hA, a.z); hB = acc_nib(hB, b.z);
    hA = acc_nib(hA, a.w); hB = acc_nib(hB, b.w);
    return hA + hB;            // nibble v = count of value v among 8 elems
}

__global__ void __launch_bounds__(256) mode_rows_kernel(
    const float4* __restrict__ xv,   // x as float4 (16 per row)
    float* __restrict__ out,
    int n_rows)
{
    const int warpId = (int)(((unsigned)blockIdx.x * blockDim.x + threadIdx.x) >> 5);
    const int lane = threadIdx.x & 31;
    const int rowBase = warpId * 16;         // 16 rows per warp
    if (rowBase >= n_rows) return;

    if (rowBase + 16 <= n_rows) {
        const int sub = lane >> 3;           // row within each 4-row group
        const int c   = lane & 7;            // chunk index 0..7
        const bool useOdd = (c & 1) != 0;    // value parity this lane owns
        const int  byteSh = (c >> 1) * 8;    // byte position of owned value
        const int  tie    = 7 - c;           // tie-break: smaller value wins

        const float4* p = xv + (size_t)(rowBase + sub) * 16 + c;

        // hoist all 8 loads (each: 8 lanes x 16B = one 128B line)
        const float4 a0 = __ldg(p +   0);    // group 0, chunk c
        const float4 b0 = __ldg(p +   8);    // group 0, chunk c+8
        const float4 a1 = __ldg(p +  64);    // group 1 (+4 rows)
        const float4 b1 = __ldg(p +  72);
        const float4 a2 = __ldg(p + 128);    // group 2 (+8 rows)
        const float4 b2 = __ldg(p + 136);
        const float4 a3 = __ldg(p + 192);    // group 3 (+12 rows)
        const float4 b3 = __ldg(p + 200);

        const unsigned h0 = hist8(a0, b0);
        const unsigned h1 = hist8(a1, b1);
        const unsigned h2 = hist8(a2, b2);
        const unsigned h3 = hist8(a3, b3);

        // widen nibbles -> bytes: even word = values {0,2,4,6}, odd = {1,3,5,7}
        unsigned e0 = h0 & 0x0F0F0F0Fu, o0 = (h0 >> 4) & 0x0F0F0F0Fu;
        unsigned e1 = h1 & 0x0F0F0F0Fu, o1 = (h1 >> 4) & 0x0F0F0F0Fu;
        unsigned e2 = h2 & 0x0F0F0F0Fu, o2 = (h2 >> 4) & 0x0F0F0F0Fu;
        unsigned e3 = h3 & 0x0F0F0F0Fu, o3 = (h3 >> 4) & 0x0F0F0F0Fu;

        // reduce over the 8 lanes of each row (xor tree stays in 8-lane group)
        #pragma unroll
        for (int m = 1; m <= 4; m <<= 1) {
            e0 += __shfl_xor_sync(0xffffffffu, e0, m);
            o0 += __shfl_xor_sync(0xffffffffu, o0, m);
            e1 += __shfl_xor_sync(0xffffffffu, e1, m);
            o1 += __shfl_xor_sync(0xffffffffu, o1, m);
            e2 += __shfl_xor_sync(0xffffffffu, e2, m);
            o2 += __shfl_xor_sync(0xffffffffu, o2, m);
            e3 += __shfl_xor_sync(0xffffffffu, e3, m);
            o3 += __shfl_xor_sync(0xffffffffu, o3, m);
        }

        // distributed mode: lane j owns value j (byte j>>1 of word j&1)
        const unsigned w0 = useOdd ? o0 : e0;
        const unsigned w1 = useOdd ? o1 : e1;
        const unsigned w2 = useOdd ? o2 : e2;
        const unsigned w3 = useOdd ? o3 : e3;
        int k0 = (int)(((w0 >> byteSh) & 0xFFu) << 3) | tie;
        int k1 = (int)(((w1 >> byteSh) & 0xFFu) << 3) | tie;
        int k2 = (int)(((w2 >> byteSh) & 0xFFu) << 3) | tie;
        int k3 = (int)(((w3 >> byteSh) & 0xFFu) << 3) | tie;
        #pragma unroll
        for (int m = 1; m <= 4; m <<= 1) {
            k0 = max(k0, __shfl_xor_sync(0xffffffffu, k0, m));
            k1 = max(k1, __shfl_xor_sync(0xffffffffu, k1, m));
            k2 = max(k2, __shfl_xor_sync(0xffffffffu, k2, m));
            k3 = max(k3, __shfl_xor_sync(0xffffffffu, k3, m));
        }

        // verified epilogue: lanes with c==0 (lanes 0,8,16,24) hold the final
        // keys for their sub-row in every group; 4 stores each.
        if (c == 0) {
            out[rowBase +      sub] = (float)(7 - (k0 & 7));
            out[rowBase +  4 + sub] = (float)(7 - (k1 & 7));
            out[rowBase +  8 + sub] = (float)(7 - (k2 & 7));
            out[rowBase + 12 + sub] = (float)(7 - (k3 & 7));
        }
    } else {
        // tail (never taken for N % 16 == 0): one row per lane, scalar
        for (int r = rowBase + lane; r < n_rows; r += 32) {
            const float* rp = (const float*)xv + (size_t)r * 64;
            int cnt[8];
            #pragma unroll
            for (int v = 0; v < 8; v++) cnt[v] = 0;
            for (int i = 0; i < 64; i++) cnt[((int)rp[i]) & 7]++;
            int bestV = 0, bestC = cnt[0];
            #pragma unroll
            for (int v = 1; v < 8; v++)
                if (cnt[v] > bestC) { bestC = cnt[v]; bestV = v; }
            out[r] = (float)bestV;
        }
    }
}

extern "C" void kernel_launch(void* const* d_in, const int* in_sizes, int n_in,
                              void* d_out, int out_size)
{
    const float* x = (const float*)d_in[0];
    float* out = (float*)d_out;

    const long long n_elems = (long long)in_sizes[0];
    const int n_rows = (int)(n_elems / 64);   // K = 64

    // 16 rows per warp, 8 warps (256 threads) per block -> 128 rows per block
    const int threads = 256;
    const int blocks = (n_rows + 127) / 128;

    mode_rows_kernel<<<blocks, threads>>>((const float4*)x, out, n_rows);
}